// round 11
// baseline (speedup 1.0000x reference)
#include <cuda_runtime.h>
#include <cstdint>
#include <cstddef>

// Problem dims
#define BB 16
#define TT 4096
#define DD 512
#define HH 512
#define NC 1536   // 3*H

typedef unsigned long long ull;

// ---------------- scratch (device globals: no runtime allocation allowed) ---
__device__ float g_xk[(size_t)BB * TT * NC];   // 402 MB: x @ kernel + bias0
__device__ float g_hbuf[2][BB][HH];            // double-buffered hidden state
__device__ int   g_ctr[16 * TT];               // per-(group,batch) per-step arrivals

// ---------------- f32x2 packed-math helpers (sm_103a) -----------------------
__device__ __forceinline__ ull pk2(float lo, float hi) {
    ull r;
    asm("mov.b64 %0, {%1, %2};" : "=l"(r) : "f"(lo), "f"(hi));
    return r;
}
__device__ __forceinline__ void unpk2(float& lo, float& hi, ull v) {
    asm("mov.b64 {%0, %1}, %2;" : "=f"(lo), "=f"(hi) : "l"(v));
}
__device__ __forceinline__ ull fma2(ull a, ull b, ull c) {
    ull d;
    asm("fma.rn.f32x2 %0, %1, %2, %3;" : "=l"(d) : "l"(a), "l"(b), "l"(c));
    return d;
}
__device__ __forceinline__ float sigmoid_f(float x) {
    return 1.f / (1.f + __expf(-x));
}
__device__ __forceinline__ float tanh_f(float x) {
    float e = __expf(2.f * x);
    return (e - 1.f) / (e + 1.f);
}

// ============================================================================
// Phase 1: xk[m][n] = sum_k x[m][k] * W[k][n] + bias0[n]
// Tile 128x128x16, 256 thr, 8x8 micro, packed fma.rn.f32x2.
// ============================================================================
#define BM 128
#define BN 128
#define BK 16

__global__ void __launch_bounds__(256, 2)
gemm_xk_kernel(const float* __restrict__ A,
               const float* __restrict__ W,
               const float* __restrict__ bias)
{
    __shared__ float As[BK][BM];
    __shared__ float Bs[BK][BN];

    const int bm  = blockIdx.y * BM;
    const int bn  = blockIdx.x * BN;
    const int tid = threadIdx.x;
    const int tx  = tid & 15;
    const int ty  = tid >> 4;

    ull accp[8][4];
#pragma unroll
    for (int i = 0; i < 8; i++)
#pragma unroll
        for (int j = 0; j < 4; j++) accp[i][j] = 0ull;

    for (int kt = 0; kt < DD; kt += BK) {
#pragma unroll
        for (int i = 0; i < 2; i++) {
            int idx = tid * 2 + i;
            int m   = idx >> 2;
            int k4  = (idx & 3) << 2;
            float4 v = *(const float4*)&A[(size_t)(bm + m) * DD + kt + k4];
            As[k4 + 0][m] = v.x;
            As[k4 + 1][m] = v.y;
            As[k4 + 2][m] = v.z;
            As[k4 + 3][m] = v.w;
        }
#pragma unroll
        for (int i = 0; i < 2; i++) {
            int idx = tid * 2 + i;
            int k   = idx >> 5;
            int n4  = (idx & 31) << 2;
            *(float4*)&Bs[k][n4] =
                *(const float4*)&W[(size_t)(kt + k) * NC + bn + n4];
        }
        __syncthreads();

#pragma unroll
        for (int k = 0; k < BK; k++) {
            float4 av0 = *(const float4*)&As[k][ty * 8];
            float4 av1 = *(const float4*)&As[k][ty * 8 + 4];
            ulonglong2 bv0 = *(const ulonglong2*)&Bs[k][tx * 8];
            ulonglong2 bv1 = *(const ulonglong2*)&Bs[k][tx * 8 + 4];
            ull bp0 = bv0.x, bp1 = bv0.y, bp2 = bv1.x, bp3 = bv1.y;
            float a[8] = {av0.x, av0.y, av0.z, av0.w,
                          av1.x, av1.y, av1.z, av1.w};
#pragma unroll
            for (int i = 0; i < 8; i++) {
                ull ap = pk2(a[i], a[i]);
                accp[i][0] = fma2(ap, bp0, accp[i][0]);
                accp[i][1] = fma2(ap, bp1, accp[i][1]);
                accp[i][2] = fma2(ap, bp2, accp[i][2]);
                accp[i][3] = fma2(ap, bp3, accp[i][3]);
            }
        }
        __syncthreads();
    }

#pragma unroll
    for (int i = 0; i < 8; i++) {
        int m = bm + ty * 8 + i;
#pragma unroll
        for (int jp = 0; jp < 2; jp++) {
            int n = bn + tx * 8 + jp * 4;
            float l0, h0, l1, h1;
            unpk2(l0, h0, accp[i][jp * 2 + 0]);
            unpk2(l1, h1, accp[i][jp * 2 + 1]);
            float4 v;
            v.x = l0 + bias[n + 0];
            v.y = h0 + bias[n + 1];
            v.z = l1 + bias[n + 2];
            v.w = h1 + bias[n + 3];
            *(float4*)&g_xk[(size_t)m * NC + n] = v;
        }
    }
}

// ============================================================================
// Phase 2: persistent GRU recurrence — batch-pipelined A/B phases.
//   8 groups x 16 CTAs; group g owns batches {2g, 2g+1}; CTA c owns units
//   [32c,32c+32). 512 thr: thread (u=lane, ks=warp) holds U[k0..k0+32) for
//   unit u's 3 gate columns (48 f32x2 regs, SHARED between both batch dots).
//   Per step (phases pipelined so each exchange RTT hides under the other
//   batch's compute):
//     A-dot(h0[t]) -> red0 -> bar -> warp0 gates -> st.cg h0[t+1], rel cA[t]
//     [t>0] wait cB[t-1] (acquire, fused chunk load) -> h_chunk1 = h1[t]
//     B-dot(h1[t]) -> red1 -> bar -> warp1 gates -> st.cg h1[t+1], rel cB[t]
//     wait cA[t] (fused) -> h_chunk0 = h0[t+1]
//   Buffer-reuse safety: consumers pass a wait only after ALL gate warps
//   released, which is after they finished reading red*/h; h ping-pong parity
//   covers the 2-step case (writer of h[t+2] must have passed wait[t]).
// ============================================================================
__global__ void __launch_bounds__(512, 1)
gru_rec_kernel(const float* __restrict__ RK,
               const float* __restrict__ bias,
               float* __restrict__ out)
{
    __shared__ float red0[16][32 * 3];     // [ks][u*3+gate]  (stride-3: no cfl)
    __shared__ float red1[16][32 * 3];
    __shared__ float h_chunk0[16][32];     // per-warp h slice, batch 0
    __shared__ float h_chunk1[16][32];     // per-warp h slice, batch 1
    __shared__ float rb_s[96];             // recurrent bias slice

    const int bx  = blockIdx.x;
    const int g   = bx >> 4;               // group 0..7
    const int c   = bx & 15;               // cta-in-group 0..15
    const int tid = threadIdx.x;
    const int u   = tid & 31;              // lane
    const int ks  = tid >> 5;              // warp / K-split 0..15
    const int jb  = c * 32;                // first unit owned
    const int b0  = g * 2;                 // first global batch
    const int k0  = ks * 32;               // this warp's K chunk

    // ---- Load U slice into registers (shared between both batches) --------
    ull ureg[3][16];
#pragma unroll
    for (int gi = 0; gi < 3; gi++)
#pragma unroll
        for (int i = 0; i < 16; i++) {
            int k = k0 + 2 * i;
            float lo = RK[(size_t)k       * NC + gi * HH + jb + u];
            float hi = RK[(size_t)(k + 1) * NC + gi * HH + jb + u];
            ureg[gi][i] = pk2(lo, hi);
        }
    if (tid < 96)
        rb_s[tid] = bias[NC + (tid >> 5) * HH + jb + (tid & 31)];
    h_chunk0[ks][u] = 0.f;                 // h0 = zeros
    h_chunk1[ks][u] = 0.f;
    __syncthreads();

    int* ctrA = &g_ctr[(g * 2 + 0) * TT];
    int* ctrB = &g_ctr[(g * 2 + 1) * TT];

    const int rl = u & 15;                 // reload pair index (lanes 0-15 real)

    float h_old = 0.f;                     // gate threads: own h from last step

    // xk prefetch for t = 0 (warp0 -> batch b0, warp1 -> batch b0+1)
    float xz = 0.f, xr = 0.f, xh = 0.f;
    size_t xbase0 = 0;
    if (ks < 2) {
        xbase0 = ((size_t)(b0 + ks) * TT) * NC + jb + u;
        xz = g_xk[xbase0];
        xr = g_xk[xbase0 + HH];
        xh = g_xk[xbase0 + 2 * HH];
    }

    for (int t = 0; t < TT; t++) {
        // ================= PHASE A : batch b0 ===============================
        {
            const ull* hp = (const ull*)h_chunk0[ks];
            ull a0 = 0, a1 = 0, a2 = 0;
#pragma unroll
            for (int i = 0; i < 16; i++) {
                ull h = hp[i];             // broadcast LDS.64
                a0 = fma2(ureg[0][i], h, a0);
                a1 = fma2(ureg[1][i], h, a1);
                a2 = fma2(ureg[2][i], h, a2);
            }
            float lo, hi;
            unpk2(lo, hi, a0); red0[ks][u * 3 + 0] = lo + hi;
            unpk2(lo, hi, a1); red0[ks][u * 3 + 1] = lo + hi;
            unpk2(lo, hi, a2); red0[ks][u * 3 + 2] = lo + hi;
        }
        __syncthreads();

        if (ks == 0) {                     // gate warp for batch b0
            float s0 = 0.f, s1 = 0.f, s2 = 0.f;
#pragma unroll
            for (int q = 0; q < 16; q++) {
                s0 += red0[q][u * 3 + 0];
                s1 += red0[q][u * 3 + 1];
                s2 += red0[q][u * 3 + 2];
            }
            s0 += rb_s[u];
            s1 += rb_s[32 + u];
            s2 += rb_s[64 + u];

            float z    = sigmoid_f(xz + s0);
            float r    = sigmoid_f(xr + s1);
            float cand = tanh_f(xh + r * s2);
            float hn   = z * h_old + (1.f - z) * cand;
            h_old = hn;

            out[((size_t)b0 * TT + t) * HH + jb + u] = hn;
            if (t == TT - 1)
                out[(size_t)BB * TT * HH + (size_t)b0 * HH + jb + u] = hn;
            asm volatile("st.global.cg.f32 [%0], %1;"
                         :: "l"(&g_hbuf[(t + 1) & 1][b0][jb + u]), "f"(hn)
                         : "memory");
            {
                size_t nb = xbase0 + (size_t)((t + 1 < TT) ? t + 1 : t) * NC;
                xz = g_xk[nb];
                xr = g_xk[nb + HH];
                xh = g_xk[nb + 2 * HH];
            }
            __syncwarp();
            if (u == 0)
                asm volatile("red.release.gpu.global.add.s32 [%0], %1;"
                             :: "l"(&ctrA[t]), "r"(1) : "memory");
        }

        // ---- wait cB[t-1] (released a full phase ago) -> h_chunk1 = h1[t] --
        if (t > 0) {
            const float* src = &g_hbuf[t & 1][b0 + 1][k0 + 2 * rl];
            int cv; ull v;
            do {
                asm volatile("ld.acquire.gpu.global.b32 %0, [%1];"
                             : "=r"(cv) : "l"(&ctrB[t - 1]) : "memory");
                asm volatile("ld.global.cg.b64 %0, [%1];"
                             : "=l"(v) : "l"(src) : "memory");
            } while (cv != 16);
            if (u < 16) *(ull*)&h_chunk1[ks][2 * rl] = v;
            __syncwarp();
        }

        // ================= PHASE B : batch b0+1 =============================
        {
            const ull* hp = (const ull*)h_chunk1[ks];
            ull a0 = 0, a1 = 0, a2 = 0;
#pragma unroll
            for (int i = 0; i < 16; i++) {
                ull h = hp[i];
                a0 = fma2(ureg[0][i], h, a0);
                a1 = fma2(ureg[1][i], h, a1);
                a2 = fma2(ureg[2][i], h, a2);
            }
            float lo, hi;
            unpk2(lo, hi, a0); red1[ks][u * 3 + 0] = lo + hi;
            unpk2(lo, hi, a1); red1[ks][u * 3 + 1] = lo + hi;
            unpk2(lo, hi, a2); red1[ks][u * 3 + 2] = lo + hi;
        }
        __syncthreads();

        if (ks == 1) {                     // gate warp for batch b0+1
            float s0 = 0.f, s1 = 0.f, s2 = 0.f;
#pragma unroll
            for (int q = 0; q < 16; q++) {
                s0 += red1[q][u * 3 + 0];
                s1 += red1[q][u * 3 + 1];
                s2 += red1[q][u * 3 + 2];
            }
            s0 += rb_s[u];
            s1 += rb_s[32 + u];
            s2 += rb_s[64 + u];

            float z    = sigmoid_f(xz + s0);
            float r    = sigmoid_f(xr + s1);
            float cand = tanh_f(xh + r * s2);
            float hn   = z * h_old + (1.f - z) * cand;
            h_old = hn;

            int gb = b0 + 1;
            out[((size_t)gb * TT + t) * HH + jb + u] = hn;
            if (t == TT - 1)
                out[(size_t)BB * TT * HH + (size_t)gb * HH + jb + u] = hn;
            asm volatile("st.global.cg.f32 [%0], %1;"
                         :: "l"(&g_hbuf[(t + 1) & 1][gb][jb + u]), "f"(hn)
                         : "memory");
            {
                size_t nb = xbase0 + (size_t)((t + 1 < TT) ? t + 1 : t) * NC;
                xz = g_xk[nb];
                xr = g_xk[nb + HH];
                xh = g_xk[nb + 2 * HH];
            }
            __syncwarp();
            if (u == 0)
                asm volatile("red.release.gpu.global.add.s32 [%0], %1;"
                             :: "l"(&ctrB[t]), "r"(1) : "memory");
        }

        // ---- wait cA[t] (B phase covered the RTT) -> h_chunk0 = h0[t+1] ----
        {
            const float* src = &g_hbuf[(t + 1) & 1][b0][k0 + 2 * rl];
            int cv; ull v;
            do {
                asm volatile("ld.acquire.gpu.global.b32 %0, [%1];"
                             : "=r"(cv) : "l"(&ctrA[t]) : "memory");
                asm volatile("ld.global.cg.b64 %0, [%1];"
                             : "=l"(v) : "l"(src) : "memory");
            } while (cv != 16);
            if (u < 16) *(ull*)&h_chunk0[ks][2 * rl] = v;
            __syncwarp();
        }
    }
}

// ============================================================================
extern "C" void kernel_launch(void* const* d_in, const int* in_sizes, int n_in,
                              void* d_out, int out_size)
{
    const float* x    = (const float*)d_in[0];   // [16,4096,512]
    const float* Wk   = (const float*)d_in[1];   // [512,1536]
    const float* RK   = (const float*)d_in[2];   // [512,1536]
    const float* bias = (const float*)d_in[3];   // [2,1536]
    float* out = (float*)d_out;                  // outputs ++ state

    // Zero the arrival counters (memset node; re-zeroed per graph replay).
    void* ctr_ptr = nullptr;
    cudaGetSymbolAddress(&ctr_ptr, g_ctr);
    cudaMemsetAsync(ctr_ptr, 0, sizeof(int) * 16 * TT);

    // Phase 1: input projection GEMM.
    dim3 grid1(NC / BN, (BB * TT) / BM);
    gemm_xk_kernel<<<grid1, 256>>>(x, Wk, bias);

    // Phase 2: persistent recurrence.
    gru_rec_kernel<<<128, 512>>>(RK, bias, out);
}

// round 12
// speedup vs baseline: 1.8045x; 1.8045x over previous
#include <cuda_runtime.h>
#include <cstdint>
#include <cstddef>

// Problem dims
#define BB 16
#define TT 4096
#define DD 512
#define HH 512
#define NC 1536   // 3*H

typedef unsigned long long ull;

// ---------------- scratch (device globals: no runtime allocation allowed) ---
__device__ float g_xk[(size_t)BB * TT * NC];   // 402 MB: x @ kernel + bias0
__device__ float g_hbuf[2][BB][HH];            // double-buffered hidden state
__device__ int   g_ctr[8 * TT];                // per-group per-step arrivals

// ---------------- f32x2 packed-math helpers (sm_103a) -----------------------
__device__ __forceinline__ ull pk2(float lo, float hi) {
    ull r;
    asm("mov.b64 %0, {%1, %2};" : "=l"(r) : "f"(lo), "f"(hi));
    return r;
}
__device__ __forceinline__ void unpk2(float& lo, float& hi, ull v) {
    asm("mov.b64 {%0, %1}, %2;" : "=f"(lo), "=f"(hi) : "l"(v));
}
__device__ __forceinline__ ull fma2(ull a, ull b, ull c) {
    ull d;
    asm("fma.rn.f32x2 %0, %1, %2, %3;" : "=l"(d) : "l"(a), "l"(b), "l"(c));
    return d;
}
__device__ __forceinline__ float sigmoid_f(float x) {
    return 1.f / (1.f + __expf(-x));
}
__device__ __forceinline__ float tanh_f(float x) {
    float e = __expf(2.f * x);
    return (e - 1.f) / (e + 1.f);
}
__device__ __forceinline__ uint32_t f2tf32(float f) {
    uint32_t r;
    asm("cvt.rna.tf32.f32 %0, %1;" : "=r"(r) : "f"(f));
    return r;
}
__device__ __forceinline__ void mma_tf32(float* c,
                                         uint32_t a0, uint32_t a1,
                                         uint32_t a2, uint32_t a3,
                                         uint32_t b0, uint32_t b1) {
    asm volatile(
        "mma.sync.aligned.m16n8k8.row.col.f32.tf32.tf32.f32 "
        "{%0,%1,%2,%3}, {%4,%5,%6,%7}, {%8,%9}, {%0,%1,%2,%3};"
        : "+f"(c[0]), "+f"(c[1]), "+f"(c[2]), "+f"(c[3])
        : "r"(a0), "r"(a1), "r"(a2), "r"(a3), "r"(b0), "r"(b1));
}

// ============================================================================
// Phase 1: xk[m][n] = sum_k x[m][k] * W[k][n] + bias0[n]   (tf32 tensor cores)
// M = 65536, K = 512, N = 1536.  BM=128, BN=64, BK=32, 256 thr (8 warps,
// 4x2 warp grid, 32x32 per warp = 2x4 m16n8k8 tiles), double-buffered smem.
// ============================================================================
#define GBM 128
#define GBN 64
#define GBK 32
#define ASTR 36   // padded A row stride (floats)
#define BSTR 68   // padded B row stride (floats)

__global__ void __launch_bounds__(256, 2)
gemm_xk_tf32(const float* __restrict__ A,
             const float* __restrict__ W,
             const float* __restrict__ bias)
{
    __shared__ float As[2][GBM][ASTR];
    __shared__ float Bs[2][GBK][BSTR];

    const int bm   = blockIdx.y * GBM;
    const int bn   = blockIdx.x * GBN;
    const int tid  = threadIdx.x;
    const int wid  = tid >> 5;
    const int lane = tid & 31;
    const int wm   = (wid & 3) * 32;    // warp row base within tile
    const int wn   = (wid >> 2) * 32;   // warp col base within tile
    const int lr   = lane >> 2;         // 0..7
    const int lc   = lane & 3;          // 0..3

    float acc[2][4][4];
#pragma unroll
    for (int mi = 0; mi < 2; mi++)
#pragma unroll
        for (int ni = 0; ni < 4; ni++)
#pragma unroll
            for (int q = 0; q < 4; q++) acc[mi][ni][q] = 0.f;

    float4 aref[4], bref[2];

    // --- tile 0 load (global -> regs -> smem) -------------------------------
#pragma unroll
    for (int i = 0; i < 4; i++) {
        int f = tid + i * 256, row = f >> 3, c4 = (f & 7) << 2;
        aref[i] = *(const float4*)&A[(size_t)(bm + row) * DD + c4];
    }
#pragma unroll
    for (int i = 0; i < 2; i++) {
        int f = tid + i * 256, k = f >> 4, n4 = (f & 15) << 2;
        bref[i] = *(const float4*)&W[(size_t)k * NC + bn + n4];
    }
#pragma unroll
    for (int i = 0; i < 4; i++) {
        int f = tid + i * 256, row = f >> 3, c4 = (f & 7) << 2;
        *(float4*)&As[0][row][c4] = aref[i];
    }
#pragma unroll
    for (int i = 0; i < 2; i++) {
        int f = tid + i * 256, k = f >> 4, n4 = (f & 15) << 2;
        *(float4*)&Bs[0][k][n4] = bref[i];
    }
    __syncthreads();

    const int NKT = DD / GBK;   // 16
    for (int kt = 0; kt < NKT; kt++) {
        const int cur = kt & 1;

        // prefetch next tile into registers (overlaps the mma work)
        if (kt < NKT - 1) {
            int kb = (kt + 1) * GBK;
#pragma unroll
            for (int i = 0; i < 4; i++) {
                int f = tid + i * 256, row = f >> 3, c4 = (f & 7) << 2;
                aref[i] = *(const float4*)&A[(size_t)(bm + row) * DD + kb + c4];
            }
#pragma unroll
            for (int i = 0; i < 2; i++) {
                int f = tid + i * 256, k = f >> 4, n4 = (f & 15) << 2;
                bref[i] = *(const float4*)&W[(size_t)(kb + k) * NC + bn + n4];
            }
        }

        // compute on smem[cur]
#pragma unroll
        for (int k8 = 0; k8 < 4; k8++) {
            uint32_t bf[4][2];
#pragma unroll
            for (int ni = 0; ni < 4; ni++) {
                int cb = wn + ni * 8;
                bf[ni][0] = f2tf32(Bs[cur][k8 * 8 + lc    ][cb + lr]);
                bf[ni][1] = f2tf32(Bs[cur][k8 * 8 + lc + 4][cb + lr]);
            }
#pragma unroll
            for (int mi = 0; mi < 2; mi++) {
                int rb = wm + mi * 16;
                uint32_t a0 = f2tf32(As[cur][rb + lr    ][k8 * 8 + lc    ]);
                uint32_t a1 = f2tf32(As[cur][rb + lr + 8][k8 * 8 + lc    ]);
                uint32_t a2 = f2tf32(As[cur][rb + lr    ][k8 * 8 + lc + 4]);
                uint32_t a3 = f2tf32(As[cur][rb + lr + 8][k8 * 8 + lc + 4]);
#pragma unroll
                for (int ni = 0; ni < 4; ni++)
                    mma_tf32(acc[mi][ni], a0, a1, a2, a3, bf[ni][0], bf[ni][1]);
            }
        }

        if (kt < NKT - 1) {
            __syncthreads();   // everyone done computing on buffer cur^1
#pragma unroll
            for (int i = 0; i < 4; i++) {
                int f = tid + i * 256, row = f >> 3, c4 = (f & 7) << 2;
                *(float4*)&As[cur ^ 1][row][c4] = aref[i];
            }
#pragma unroll
            for (int i = 0; i < 2; i++) {
                int f = tid + i * 256, k = f >> 4, n4 = (f & 15) << 2;
                *(float4*)&Bs[cur ^ 1][k][n4] = bref[i];
            }
            __syncthreads();
        }
    }

    // epilogue: add input bias, store fp32
#pragma unroll
    for (int mi = 0; mi < 2; mi++) {
#pragma unroll
        for (int ni = 0; ni < 4; ni++) {
            int r0 = bm + wm + mi * 16 + lr;
            int c0 = bn + wn + ni * 8 + lc * 2;
            float bz0 = bias[c0], bz1 = bias[c0 + 1];
            float2 v0 = make_float2(acc[mi][ni][0] + bz0, acc[mi][ni][1] + bz1);
            float2 v1 = make_float2(acc[mi][ni][2] + bz0, acc[mi][ni][3] + bz1);
            *(float2*)&g_xk[(size_t)r0 * NC + c0]       = v0;
            *(float2*)&g_xk[(size_t)(r0 + 8) * NC + c0] = v1;
        }
    }
}

// ============================================================================
// Phase 2: persistent GRU recurrence — EXACT R10 structure (proven 11.98 ms).
//   U in registers, release/acquire sync, fused acquire-poll + chunk reload.
// ============================================================================
__global__ void __launch_bounds__(512, 1)
gru_rec_kernel(const float* __restrict__ RK,
               const float* __restrict__ bias,
               float* __restrict__ out)
{
    __shared__ float red[16][32][7];       // [ks][u][gate*2+b]
    __shared__ float h_chunk[16][2][32];   // per-warp private h slice
    __shared__ float rb_s[96];             // recurrent bias slice

    const int bx  = blockIdx.x;
    const int g   = bx >> 4;               // group 0..7
    const int c   = bx & 15;               // cta-in-group 0..15
    const int tid = threadIdx.x;
    const int u   = tid & 31;              // lane
    const int ks  = tid >> 5;              // warp / K-split 0..15
    const int jb  = c * 32;                // first unit owned
    const int b0  = g * 2;                 // first global batch
    const int k0  = ks * 32;               // this warp's K chunk

    // ---- Load U slice into registers ---------------------------------------
    ull ureg[3][16];
#pragma unroll
    for (int gi = 0; gi < 3; gi++)
#pragma unroll
        for (int i = 0; i < 16; i++) {
            int k = k0 + 2 * i;
            float lo = RK[(size_t)k       * NC + gi * HH + jb + u];
            float hi = RK[(size_t)(k + 1) * NC + gi * HH + jb + u];
            ureg[gi][i] = pk2(lo, hi);
        }
    if (tid < 96)
        rb_s[tid] = bias[NC + (tid >> 5) * HH + jb + (tid & 31)];
    // zero own h chunk (h0 = 0)
    for (int i = u; i < 64; i += 32) ((float*)h_chunk[ks])[i] = 0.f;
    __syncthreads();

    int* ctr = &g_ctr[g * TT];

    // reload-phase lane mapping: lane -> (batch, pair-index)
    const int rl_b = u >> 4;               // 0..1
    const int rl_l = u & 15;               // 0..15

    float h_old = 0.f;                     // gate threads: own h from last step

    // xk prefetch for t = 0 (gate warps only)
    float xz = 0.f, xr = 0.f, xh = 0.f;
    size_t xbase0 = 0;
    if (ks < 2) {
        xbase0 = ((size_t)(b0 + ks) * TT) * NC + jb + u;
        xz = g_xk[xbase0];
        xr = g_xk[xbase0 + HH];
        xh = g_xk[xbase0 + 2 * HH];
    }

    for (int t = 0; t < TT; t++) {
        // ---- packed dot over own 32-wide K chunk ---------------------------
        const ull* hp0 = (const ull*)h_chunk[ks][0];
        const ull* hp1 = (const ull*)h_chunk[ks][1];
        ull a0 = 0, a1 = 0, a2 = 0, a3 = 0, a4 = 0, a5 = 0;
#pragma unroll
        for (int i = 0; i < 16; i++) {
            ull h0 = hp0[i];               // broadcast LDS.64
            ull h1 = hp1[i];
            a0 = fma2(ureg[0][i], h0, a0);
            a1 = fma2(ureg[1][i], h0, a1);
            a2 = fma2(ureg[2][i], h0, a2);
            a3 = fma2(ureg[0][i], h1, a3);
            a4 = fma2(ureg[1][i], h1, a4);
            a5 = fma2(ureg[2][i], h1, a5);
        }
        {
            float lo, hi;
            unpk2(lo, hi, a0); red[ks][u][0] = lo + hi;   // z, b0
            unpk2(lo, hi, a1); red[ks][u][2] = lo + hi;   // r, b0
            unpk2(lo, hi, a2); red[ks][u][4] = lo + hi;   // h, b0
            unpk2(lo, hi, a3); red[ks][u][1] = lo + hi;   // z, b1
            unpk2(lo, hi, a4); red[ks][u][3] = lo + hi;   // r, b1
            unpk2(lo, hi, a5); red[ks][u][5] = lo + hi;   // h, b1
        }
        __syncthreads();

        // ---- gate warps: reduce + gates + publish + release-signal ---------
        if (ks < 2) {
            float s0 = 0.f, s1 = 0.f, s2 = 0.f;
#pragma unroll
            for (int q = 0; q < 16; q++) {
                s0 += red[q][u][0 + ks];
                s1 += red[q][u][2 + ks];
                s2 += red[q][u][4 + ks];
            }
            s0 += rb_s[u];
            s1 += rb_s[32 + u];
            s2 += rb_s[64 + u];

            float z    = sigmoid_f(xz + s0);
            float r    = sigmoid_f(xr + s1);
            float cand = tanh_f(xh + r * s2);
            float hn   = z * h_old + (1.f - z) * cand;
            h_old = hn;

            int gb = b0 + ks;
            out[((size_t)gb * TT + t) * HH + jb + u] = hn;
            if (t == TT - 1)
                out[(size_t)BB * TT * HH + (size_t)gb * HH + jb + u] = hn;
            asm volatile("st.global.cg.f32 [%0], %1;"
                         :: "l"(&g_hbuf[(t + 1) & 1][gb][jb + u]), "f"(hn)
                         : "memory");

            // prefetch next step's xk (consumed next iteration)
            {
                size_t nb = xbase0 + (size_t)((t + 1 < TT) ? t + 1 : t) * NC;
                xz = g_xk[nb];
                xr = g_xk[nb + HH];
                xh = g_xk[nb + 2 * HH];
            }

            __syncwarp();                  // warp stores HB-before lane0's RED
            if (u == 0)
                asm volatile("red.release.gpu.global.add.s32 [%0], %1;"
                             :: "l"(&ctr[t]), "r"(1) : "memory");
        }

        // ---- fused acquire-poll + own-chunk reload -------------------------
        {
            const float* src = &g_hbuf[(t + 1) & 1][b0 + rl_b][k0 + 2 * rl_l];
            int cv;
            ull v;
            do {
                asm volatile("ld.acquire.gpu.global.b32 %0, [%1];"
                             : "=r"(cv) : "l"(&ctr[t]) : "memory");
                asm volatile("ld.global.cg.b64 %0, [%1];"
                             : "=l"(v) : "l"(src) : "memory");
            } while (cv != 32);
            // loop exits => the b64 load above was issued after a successful
            // acquire of ctr==32, so v is the committed h' value.
            *(ull*)&h_chunk[ks][rl_b][2 * rl_l] = v;
        }
        __syncwarp();
    }
}

// ============================================================================
extern "C" void kernel_launch(void* const* d_in, const int* in_sizes, int n_in,
                              void* d_out, int out_size)
{
    const float* x    = (const float*)d_in[0];   // [16,4096,512]
    const float* Wk   = (const float*)d_in[1];   // [512,1536]
    const float* RK   = (const float*)d_in[2];   // [512,1536]
    const float* bias = (const float*)d_in[3];   // [2,1536]
    float* out = (float*)d_out;                  // outputs ++ state

    // Zero the arrival counters (memset node; re-zeroed per graph replay).
    void* ctr_ptr = nullptr;
    cudaGetSymbolAddress(&ctr_ptr, g_ctr);
    cudaMemsetAsync(ctr_ptr, 0, sizeof(int) * 8 * TT);

    // Phase 1: input projection GEMM (tf32 tensor cores).
    dim3 grid1(NC / GBN, (BB * TT) / GBM);
    gemm_xk_tf32<<<grid1, 256>>>(x, Wk, bias);

    // Phase 2: persistent recurrence (exact R10 kernel).
    gru_rec_kernel<<<128, 512>>>(RK, bias, out);
}